// round 10
// baseline (speedup 1.0000x reference)
#include <cuda_runtime.h>
#include <cuda_bf16.h>

// Problem shape (FeatureGradFetcher): B=2, V=5, C=16, H=512, W=640, N=131072
#define BB 2
#define VV 5
#define CC 16
#define HH 512
#define WW 640
#define HW_ (HH * WW)          // 327680
#define NBV (BB * VV)          // 10

// Scratch: feature maps transposed to (bv, h, w, c): one pixel's 16 channels
// are 64 contiguous, 64B-aligned bytes. ~210 MB, static __device__ (no allocs).
__device__ float g_fmT[(size_t)NBV * HW_ * CC];

// Streaming (evict-first) stores: data written once, not re-read soon.
__device__ __forceinline__ void st_cs(float* p, float v) {
    asm volatile("st.global.cs.f32 [%0], %1;" :: "l"(p), "f"(v) : "memory");
}
__device__ __forceinline__ void st_cs_v2(float2* p, float2 v) {
    asm volatile("st.global.cs.v2.f32 [%0], {%1, %2};" :: "l"(p), "f"(v.x), "f"(v.y) : "memory");
}
__device__ __forceinline__ void st_cs_v4(float4* p, float4 v) {
    asm volatile("st.global.cs.v4.f32 [%0], {%1, %2, %3, %4};"
                 :: "l"(p), "f"(v.x), "f"(v.y), "f"(v.z), "f"(v.w) : "memory");
}

__device__ __forceinline__ float4 lerp4(float4 a, float4 b, float w) {
    float4 r;
    r.x = fmaf(w, b.x - a.x, a.x);
    r.y = fmaf(w, b.y - a.y, a.y);
    r.z = fmaf(w, b.z - a.z, a.z);
    r.w = fmaf(w, b.w - a.w, a.w);
    return r;
}
__device__ __forceinline__ float4 shfl_down4(float4 v, int d) {
    float4 r;
    r.x = __shfl_down_sync(0xffffffffu, v.x, d);
    r.y = __shfl_down_sync(0xffffffffu, v.y, d);
    r.z = __shfl_down_sync(0xffffffffu, v.z, d);
    r.w = __shfl_down_sync(0xffffffffu, v.w, d);
    return r;
}
__device__ __forceinline__ float4 shfl_up4(float4 v, int d) {
    float4 r;
    r.x = __shfl_up_sync(0xffffffffu, v.x, d);
    r.y = __shfl_up_sync(0xffffffffu, v.y, d);
    r.z = __shfl_up_sync(0xffffffffu, v.z, d);
    r.w = __shfl_up_sync(0xffffffffu, v.w, d);
    return r;
}
__device__ __forceinline__ float4 shfl_xor4(float4 v, int m) {
    float4 r;
    r.x = __shfl_xor_sync(0xffffffffu, v.x, m);
    r.y = __shfl_xor_sync(0xffffffffu, v.y, m);
    r.z = __shfl_xor_sync(0xffffffffu, v.z, m);
    r.w = __shfl_xor_sync(0xffffffffu, v.w, m);
    return r;
}

// ---------------------------------------------------------------------------
// Kernel 1: transpose (bv, c, h, w) -> (bv, hw, c) via smem tiles.
// ---------------------------------------------------------------------------
__global__ void __launch_bounds__(256) transpose_kernel(const float* __restrict__ fm) {
    __shared__ float tile[CC][64 + 1];

    const int bv   = blockIdx.y;
    const int pix0 = blockIdx.x * 64;
    const int tid  = threadIdx.x;

    const int pix = tid & 63;
    const int c0  = tid >> 6;

    const float* src = fm + (size_t)bv * CC * HW_ + pix0 + pix;
#pragma unroll
    for (int i = 0; i < 4; i++) {
        int c = i * 4 + c0;
        tile[c][pix] = __ldg(src + (size_t)c * HW_);
    }
    __syncthreads();

    float4* dst = (float4*)(g_fmT + ((size_t)bv * HW_ + pix0) * CC);
    const int p  = tid >> 2;
    const int cw = (tid & 3) * 4;
    float4 v;
    v.x = tile[cw + 0][p];
    v.y = tile[cw + 1][p];
    v.z = tile[cw + 2][p];
    v.w = tile[cw + 3][p];
    st_cs_v4(dst + tid, v);
}

// ---------------------------------------------------------------------------
// Fallback bilinear (exact reference math, bounds-checked), one cg chunk.
// ---------------------------------------------------------------------------
__device__ float4 bilin_clip(const float* __restrict__ fbcg, float gx_, float gy_) {
    const float ixs = ((gx_ + 1.0f) * (float)WW - 1.0f) * 0.5f;
    const float iys = ((gy_ + 1.0f) * (float)HH - 1.0f) * 0.5f;
    const float x0f = floorf(ixs);
    const float y0f = floorf(iys);
    const float wx1 = ixs - x0f;
    const float wy1 = iys - y0f;
    const float wx0 = 1.0f - wx1;
    const float wy0 = 1.0f - wy1;
    const int sx0 = (int)x0f;
    const int sy0 = (int)y0f;

    const int   xs[2]  = {sx0, sx0 + 1};
    const int   ys[2]  = {sy0, sy0 + 1};
    const float wxs[2] = {wx0, wx1};
    const float wys[2] = {wy0, wy1};

    float4 acc = make_float4(0.f, 0.f, 0.f, 0.f);
#pragma unroll
    for (int tyi = 0; tyi < 2; tyi++) {
#pragma unroll
        for (int txi = 0; txi < 2; txi++) {
            const int xi = xs[txi];
            const int yi = ys[tyi];
            if (xi >= 0 && xi < WW && yi >= 0 && yi < HH) {
                const float w = wxs[txi] * wys[tyi];
                const float4 d = __ldg((const float4*)(fbcg + ((size_t)yi * WW + xi) * CC));
                acc.x = fmaf(w, d.x, acc.x);
                acc.y = fmaf(w, d.y, acc.y);
                acc.z = fmaf(w, d.z, acc.z);
                acc.w = fmaf(w, d.w, acc.w);
            }
        }
    }
    return acc;
}

// ---------------------------------------------------------------------------
// Kernel 2: project + 5x bilinear + gradients.
// Warp = 2 points x 16 lanes (4 pixel-columns x 4 channel-groups).
// Fast path: 3 warp loads cover the 12-texel cross per point (8 line-touches,
// the distinct-line floor). Results staged in smem, stored coalesced.
// ---------------------------------------------------------------------------
__global__ void __launch_bounds__(256) sample_kernel(
    const float* __restrict__ pts,      // (B, 3, N)
    const float* __restrict__ Kall,     // (B, V, 3, 3)
    const float* __restrict__ Eall,     // (B, V, 3, 4)
    float* __restrict__ out,            // f (BV,C,N) then f_grad (BV,C,N,2)
    int Npts)
{
    __shared__ float sC[CC][17], sL[CC][17], sR[CC][17], sT[CC][17], sB[CC][17];

    const int bv     = blockIdx.y;
    const int tid    = threadIdx.x;
    const int lane   = tid & 31;
    const int warpId = tid >> 5;
    const int sub    = lane >> 4;        // point within warp: 0..1
    const int g16    = lane & 15;
    const int px     = g16 >> 2;         // pixel-column role: 0..3
    const int cg     = g16 & 3;          // channel group: 0..3

    const int ptInBlk = warpId * 2 + sub;            // 0..15
    int n = blockIdx.x * 16 + ptInBlk;
    const bool valid = (n < Npts);
    if (n >= Npts) n = Npts - 1;                     // clamp; stores guarded

    const int b = bv / VV;

    // --- geometry (identical per lane of a point) ---
    const float* E = Eall + bv * 12;
    const float* K = Kall + bv * 9;
    const size_t pb = (size_t)b * 3 * Npts + n;
    const float p_x = __ldg(pts + pb);
    const float p_y = __ldg(pts + pb + Npts);
    const float p_z = __ldg(pts + pb + 2 * (size_t)Npts);

    const float tx = fmaf(__ldg(E + 0), p_x, fmaf(__ldg(E + 1), p_y, fmaf(__ldg(E + 2),  p_z, __ldg(E + 3))));
    const float ty = fmaf(__ldg(E + 4), p_x, fmaf(__ldg(E + 5), p_y, fmaf(__ldg(E + 6),  p_z, __ldg(E + 7))));
    const float tz = fmaf(__ldg(E + 8), p_x, fmaf(__ldg(E + 9), p_y, fmaf(__ldg(E + 10), p_z, __ldg(E + 11))));

    const float rz = 1.0f / tz;
    const float nxv = tx * rz;
    const float nyv = ty * rz;
    const float u  = fmaf(__ldg(K + 0), nxv, fmaf(__ldg(K + 1), nyv, __ldg(K + 2)));
    const float v  = fmaf(__ldg(K + 3), nxv, fmaf(__ldg(K + 4), nyv, __ldg(K + 5)));

    const float gx = (u - 0.5f) / (float)(WW - 1) * 2.0f - 1.0f;
    const float gy = (v - 0.5f) / (float)(HH - 1) * 2.0f - 1.0f;
    const float dx = 2.0f / (float)(WW - 1);
    const float dy = 2.0f / (float)(HH - 1);

    const float ix = ((gx + 1.0f) * (float)WW - 1.0f) * 0.5f;
    const float iy = ((gy + 1.0f) * (float)HH - 1.0f) * 0.5f;
    const float x0f = floorf(ix);
    const float y0f = floorf(iy);
    const float fx = ix - x0f;
    const float fy = iy - y0f;
    const int x0 = (int)x0f;
    const int y0 = (int)y0f;

    const float ex = 1.0f / (float)(WW - 1);
    const float ey = 1.0f / (float)(HH - 1);

    const bool fast =
        (fx >= ex) && (fx < 1.0f - ex) &&
        (fy >= ey) && (fy < 1.0f - ey) &&
        (x0 >= 1) && (x0 <= WW - 3) && (y0 >= 1) && (y0 <= HH - 3);
    // Warp-uniform branch: shfls below require full-warp participation.
    const bool warpFast = __all_sync(0xffffffffu, fast);

    const float* fbase = g_fmT + (size_t)bv * HW_ * CC;

    if (warpFast) {
        // --- 3 loads cover the whole 12-texel cross for this point ---
        // rM: row y0,   pixel x0-1+px   (4-px span)
        // rN: row y0+1, pixel x0-1+px
        // rTB: px<2 -> row y0-1, pixel x0+px ; px>=2 -> row y0+2, pixel x0+(px-2)
        const float4 rM = __ldg((const float4*)(fbase + ((size_t)y0 * WW + (x0 - 1 + px)) * CC + cg * 4));
        const float4 rN = __ldg((const float4*)(fbase + ((size_t)(y0 + 1) * WW + (x0 - 1 + px)) * CC + cg * 4));
        const int tbRow = (px < 2) ? (y0 - 1) : (y0 + 2);
        const int tbPx  = x0 + (px & 1);
        const float4 rTB = __ldg((const float4*)(fbase + ((size_t)tbRow * WW + tbPx) * CC + cg * 4));

        // Redistribute: +4 lanes = next pixel column (same point, same cg).
        const float4 dM = shfl_down4(rM, 4);   // px -> px+1's rM
        const float4 dN = shfl_down4(rN, 4);
        const float4 uN = shfl_up4(rN, 4);     // px -> px-1's rN
        const float4 xT = shfl_xor4(rTB, 4);   // pair partner within T / B rows

        const float fxl = fx - ex, fxr = fx + ex;
        const float fyt = fy - ey, fyb = fy + ey;

        if (px == 0) {
            // fL: cols (x0-1, x0) at weight fxl
            const float4 hC = lerp4(rM, dM, fxl);
            const float4 hN = lerp4(rN, dN, fxl);
            const float4 fL = lerp4(hC, hN, fy);
            sL[cg * 4 + 0][ptInBlk] = fL.x; sL[cg * 4 + 1][ptInBlk] = fL.y;
            sL[cg * 4 + 2][ptInBlk] = fL.z; sL[cg * 4 + 3][ptInBlk] = fL.w;
        } else if (px == 1) {
            // fC: cols (x0, x0+1) at fx;  fT: rowT lerp then vertical at fyt
            const float4 hCC = lerp4(rM, dM, fx);
            const float4 hNC = lerp4(rN, dN, fx);
            const float4 fC = lerp4(hCC, hNC, fy);
            const float4 hT = lerp4(xT, rTB, fx);    // a (px0's rTB), b (own)
            const float4 fT = lerp4(hT, hCC, fyt);
            sC[cg * 4 + 0][ptInBlk] = fC.x; sC[cg * 4 + 1][ptInBlk] = fC.y;
            sC[cg * 4 + 2][ptInBlk] = fC.z; sC[cg * 4 + 3][ptInBlk] = fC.w;
            sT[cg * 4 + 0][ptInBlk] = fT.x; sT[cg * 4 + 1][ptInBlk] = fT.y;
            sT[cg * 4 + 2][ptInBlk] = fT.z; sT[cg * 4 + 3][ptInBlk] = fT.w;
        } else if (px == 2) {
            // fR: cols (x0+1, x0+2) at fxr;  fB: rowB lerp then vertical at fyb
            const float4 hCR = lerp4(rM, dM, fxr);
            const float4 hNR = lerp4(rN, dN, fxr);
            const float4 fR = lerp4(hCR, hNR, fy);
            const float4 hB  = lerp4(rTB, xT, fx);   // k (own), l (px3's rTB)
            const float4 hNC = lerp4(uN, rN, fx);    // d_N (px1's rN), e_N (own)
            const float4 fB = lerp4(hNC, hB, fyb);
            sR[cg * 4 + 0][ptInBlk] = fR.x; sR[cg * 4 + 1][ptInBlk] = fR.y;
            sR[cg * 4 + 2][ptInBlk] = fR.z; sR[cg * 4 + 3][ptInBlk] = fR.w;
            sB[cg * 4 + 0][ptInBlk] = fB.x; sB[cg * 4 + 1][ptInBlk] = fB.y;
            sB[cg * 4 + 2][ptInBlk] = fB.z; sB[cg * 4 + 3][ptInBlk] = fB.w;
        }
    } else {
        // Whole-warp fallback: exact reference math, bounds-checked.
        const float* fbcg = fbase + cg * 4;
        if (px == 0) {
            const float4 fL = bilin_clip(fbcg, gx - dx, gy);
            sL[cg * 4 + 0][ptInBlk] = fL.x; sL[cg * 4 + 1][ptInBlk] = fL.y;
            sL[cg * 4 + 2][ptInBlk] = fL.z; sL[cg * 4 + 3][ptInBlk] = fL.w;
        } else if (px == 1) {
            const float4 fC = bilin_clip(fbcg, gx, gy);
            const float4 fT = bilin_clip(fbcg, gx, gy - dy);
            sC[cg * 4 + 0][ptInBlk] = fC.x; sC[cg * 4 + 1][ptInBlk] = fC.y;
            sC[cg * 4 + 2][ptInBlk] = fC.z; sC[cg * 4 + 3][ptInBlk] = fC.w;
            sT[cg * 4 + 0][ptInBlk] = fT.x; sT[cg * 4 + 1][ptInBlk] = fT.y;
            sT[cg * 4 + 2][ptInBlk] = fT.z; sT[cg * 4 + 3][ptInBlk] = fT.w;
        } else if (px == 2) {
            const float4 fR = bilin_clip(fbcg, gx + dx, gy);
            const float4 fB = bilin_clip(fbcg, gx, gy + dy);
            sR[cg * 4 + 0][ptInBlk] = fR.x; sR[cg * 4 + 1][ptInBlk] = fR.y;
            sR[cg * 4 + 2][ptInBlk] = fR.z; sR[cg * 4 + 3][ptInBlk] = fR.w;
            sB[cg * 4 + 0][ptInBlk] = fB.x; sB[cg * 4 + 1][ptInBlk] = fB.y;
            sB[cg * 4 + 2][ptInBlk] = fB.z; sB[cg * 4 + 3][ptInBlk] = fB.w;
        }
    }

    __syncthreads();

    // --- coalesced store phase ---
    // 256 threads: tid -> (ch = tid>>4, pt = tid&15); 16 consecutive n per block.
    {
        const int ch = tid >> 4;
        const int pt = tid & 15;
        const int nn = blockIdx.x * 16 + pt;
        if (nn < Npts) {
            float* outF = out;
            st_cs(outF + ((size_t)bv * CC + ch) * Npts + nn, sC[ch][pt]);

            float2* outG = (float2*)(out + (size_t)NBV * CC * Npts);
            float2 g;
            g.x = 0.5f * (sR[ch][pt] - sL[ch][pt]);
            g.y = 0.5f * (sB[ch][pt] - sT[ch][pt]);
            st_cs_v2(outG + ((size_t)bv * CC + ch) * Npts + nn, g);
        }
    }
    (void)valid;
}

// ---------------------------------------------------------------------------
// Launch. Inputs resolved by SIZE fingerprint:
//   fm = 52,428,800   pts = 786,432   K = 90   E = 120
// ---------------------------------------------------------------------------
extern "C" void kernel_launch(void* const* d_in, const int* in_sizes, int n_in,
                              void* d_out, int out_size) {
    const float* fm  = nullptr;
    const float* pts = nullptr;
    const float* K   = nullptr;
    const float* E   = nullptr;
    int pts_size = 0;

    for (int i = 0; i < n_in; i++) {
        const int s = in_sizes[i];
        if (s == NBV * 9) {
            K = (const float*)d_in[i];
        } else if (s == NBV * 12) {
            E = (const float*)d_in[i];
        } else if (s == (int)((size_t)NBV * CC * HW_)) {
            fm = (const float*)d_in[i];
        } else {
            pts = (const float*)d_in[i];
            pts_size = s;
        }
    }
    if (!fm || !pts || !K || !E) {
        fm  = (const float*)d_in[0];
        pts = (const float*)d_in[1];
        K   = (const float*)d_in[2];
        E   = (const float*)d_in[3];
        pts_size = in_sizes[1];
    }

    float* out = (float*)d_out;
    const int Npts = pts_size / (BB * 3);   // pts is (B, 3, N)

    dim3 tgrid(HW_ / 64, NBV);
    transpose_kernel<<<tgrid, 256>>>(fm);

    dim3 sgrid((Npts + 15) / 16, NBV);
    sample_kernel<<<sgrid, 256>>>(pts, K, E, out, Npts);
}

// round 15
// speedup vs baseline: 1.1443x; 1.1443x over previous
#include <cuda_runtime.h>
#include <cuda_bf16.h>

// Problem shape (FeatureGradFetcher): B=2, V=5, C=16, H=512, W=640, N=131072
#define BB 2
#define VV 5
#define CC 16
#define HH 512
#define WW 640
#define HW_ (HH * WW)          // 327680
#define NBV (BB * VV)          // 10

// Scratch: feature maps transposed to (bv, h, w, c) so one pixel's 16 channels
// are 64 contiguous, 64B-aligned bytes. ~210 MB, static __device__ (no allocs).
__device__ float g_fmT[(size_t)NBV * HW_ * CC];

// Streaming (evict-first) stores: data written once, not re-read soon.
__device__ __forceinline__ void st_cs_v4(float4* p, float4 v) {
    asm volatile("st.global.cs.v4.f32 [%0], {%1, %2, %3, %4};"
                 :: "l"(p), "f"(v.x), "f"(v.y), "f"(v.z), "f"(v.w) : "memory");
}

// ---------------------------------------------------------------------------
// Kernel 1: transpose (bv, c, h, w) -> (bv, hw, c) via smem tiles.
// ---------------------------------------------------------------------------
__global__ void __launch_bounds__(256) transpose_kernel(const float* __restrict__ fm) {
    __shared__ float tile[CC][64 + 1];

    const int bv   = blockIdx.y;
    const int pix0 = blockIdx.x * 64;
    const int tid  = threadIdx.x;

    const int pix = tid & 63;   // 0..63
    const int c0  = tid >> 6;   // 0..3

    const float* src = fm + (size_t)bv * CC * HW_ + pix0 + pix;
#pragma unroll
    for (int i = 0; i < 4; i++) {
        int c = i * 4 + c0;
        tile[c][pix] = __ldg(src + (size_t)c * HW_);
    }
    __syncthreads();

    float4* dst = (float4*)(g_fmT + ((size_t)bv * HW_ + pix0) * CC);
    const int p  = tid >> 2;        // pixel within tile, 0..63
    const int cw = (tid & 3) * 4;   // starting channel, {0,4,8,12}
    float4 v;
    v.x = tile[cw + 0][p];
    v.y = tile[cw + 1][p];
    v.z = tile[cw + 2][p];
    v.w = tile[cw + 3][p];
    st_cs_v4(dst + tid, v);
}

// ---------------------------------------------------------------------------
// Kernel 2: project + 5x bilinear sample + gradients.
// Lane mapping (MEASURED-GOOD R5 structure): warp = 8 points x 4 channel-
// groups; each tap is one LDG.128 per lane, 4 lanes of a point share a 128B
// line. Fast path: 12-texel cross (floors align for ~99% of points); exact
// 20-tap fallback otherwise. NEW vs R5: results staged in smem and stored
// block-wide coalesced (cuts store wavefronts ~4 -> ~1.5 per point).
// ---------------------------------------------------------------------------
__global__ void __launch_bounds__(256) sample_kernel(
    const float* __restrict__ pts,      // (B, 3, N)
    const float* __restrict__ Kall,     // (B, V, 3, 3)
    const float* __restrict__ Eall,     // (B, V, 3, 4)
    float* __restrict__ out,            // f (BV,C,N) then f_grad (BV,C,N,2)
    int Npts)
{
    // Pitch 66: addr = ch*66 + pt; bank = (2*ch + pt) mod 32 across the warp's
    // (cg 0..3 x pt 0..7) is unique for each k -> conflict-free staging.
    __shared__ float sF [CC][66];
    __shared__ float sGx[CC][66];
    __shared__ float sGy[CC][66];

    const int bv        = blockIdx.y;
    const int tid       = threadIdx.x;
    const int lane      = tid & 31;
    const int warpInBlk = tid >> 5;
    const int cg        = lane >> 3;                  // channel group 0..3
    const int ptInBlk   = warpInBlk * 8 + (lane & 7); // 0..63
    int n = blockIdx.x * 64 + ptInBlk;
    if (n >= Npts) n = Npts - 1;                      // clamp; stores guarded

    const int b = bv / VV;

    // --- geometry ---
    const float* E = Eall + bv * 12;   // row-major 3x4
    const float* K = Kall + bv * 9;    // row-major 3x3
    const size_t pb = (size_t)b * 3 * Npts + n;
    const float px = __ldg(pts + pb);
    const float py = __ldg(pts + pb + Npts);
    const float pz = __ldg(pts + pb + 2 * (size_t)Npts);

    const float tx = fmaf(__ldg(E + 0), px, fmaf(__ldg(E + 1), py, fmaf(__ldg(E + 2),  pz, __ldg(E + 3))));
    const float ty = fmaf(__ldg(E + 4), px, fmaf(__ldg(E + 5), py, fmaf(__ldg(E + 6),  pz, __ldg(E + 7))));
    const float tz = fmaf(__ldg(E + 8), px, fmaf(__ldg(E + 9), py, fmaf(__ldg(E + 10), pz, __ldg(E + 11))));

    const float rz = 1.0f / tz;
    const float nx = tx * rz;
    const float ny = ty * rz;
    const float u  = fmaf(__ldg(K + 0), nx, fmaf(__ldg(K + 1), ny, __ldg(K + 2)));
    const float v  = fmaf(__ldg(K + 3), nx, fmaf(__ldg(K + 4), ny, __ldg(K + 5)));

    const float gx = (u - 0.5f) / (float)(WW - 1) * 2.0f - 1.0f;
    const float gy = (v - 0.5f) / (float)(HH - 1) * 2.0f - 1.0f;
    const float dx = 2.0f / (float)(WW - 1);
    const float dy = 2.0f / (float)(HH - 1);

    // Center sample pixel coords
    const float ix = ((gx + 1.0f) * (float)WW - 1.0f) * 0.5f;
    const float iy = ((gy + 1.0f) * (float)HH - 1.0f) * 0.5f;
    const float x0f = floorf(ix);
    const float y0f = floorf(iy);
    const float fx = ix - x0f;
    const float fy = iy - y0f;
    const int x0 = (int)x0f;
    const int y0 = (int)y0f;

    // Neighbor samples shift by W/(W-1) = 1 + ex pixels (NOT exactly 1).
    const float ex = 1.0f / (float)(WW - 1);
    const float ey = 1.0f / (float)(HH - 1);

    const float* fb = g_fmT + (size_t)bv * HW_ * CC + cg * 4;

    float fC[4], fL[4], fR[4], fT[4], fB4[4];

    const bool fast =
        (fx >= ex) && (fx < 1.0f - ex) &&
        (fy >= ey) && (fy < 1.0f - ey) &&
        (x0 >= 1) && (x0 <= WW - 3) && (y0 >= 1) && (y0 <= HH - 3);

    if (fast) {
        // 12-texel cross: rows y0-1..y0+2, cols x0-1..x0+2, minus the 4 corners.
        const float fxl = fx - ex, fxr = fx + ex;
        const float fyt = fy - ey, fyb = fy + ey;

        const size_t rowStride = (size_t)WW * CC;
        const float* base = fb + ((size_t)y0 * WW + x0) * CC;   // texel (x0, y0)

        const float4 A  = __ldg((const float4*)(base - rowStride));            // (x0,  y0-1)
        const float4 Bx = __ldg((const float4*)(base - rowStride + CC));       // (x0+1,y0-1)
        const float4 Cx = __ldg((const float4*)(base - CC));                   // (x0-1,y0)
        const float4 D  = __ldg((const float4*)(base));                        // (x0,  y0)
        const float4 Ex = __ldg((const float4*)(base + CC));                   // (x0+1,y0)
        const float4 F  = __ldg((const float4*)(base + 2 * CC));               // (x0+2,y0)
        const float4 G  = __ldg((const float4*)(base + rowStride - CC));       // (x0-1,y0+1)
        const float4 Hx = __ldg((const float4*)(base + rowStride));            // (x0,  y0+1)
        const float4 I  = __ldg((const float4*)(base + rowStride + CC));       // (x0+1,y0+1)
        const float4 J  = __ldg((const float4*)(base + rowStride + 2 * CC));   // (x0+2,y0+1)
        const float4 K2 = __ldg((const float4*)(base + 2 * rowStride));        // (x0,  y0+2)
        const float4 L  = __ldg((const float4*)(base + 2 * rowStride + CC));   // (x0+1,y0+2)

        const float a_[4]  = {A.x, A.y, A.z, A.w};
        const float b_[4]  = {Bx.x, Bx.y, Bx.z, Bx.w};
        const float c_[4]  = {Cx.x, Cx.y, Cx.z, Cx.w};
        const float d_[4]  = {D.x, D.y, D.z, D.w};
        const float e_[4]  = {Ex.x, Ex.y, Ex.z, Ex.w};
        const float f_[4]  = {F.x, F.y, F.z, F.w};
        const float g_[4]  = {G.x, G.y, G.z, G.w};
        const float h_[4]  = {Hx.x, Hx.y, Hx.z, Hx.w};
        const float i_[4]  = {I.x, I.y, I.z, I.w};
        const float j_[4]  = {J.x, J.y, J.z, J.w};
        const float k_[4]  = {K2.x, K2.y, K2.z, K2.w};
        const float l_[4]  = {L.x, L.y, L.z, L.w};

#pragma unroll
        for (int k = 0; k < 4; k++) {
            const float rowC_c = fmaf(fx,  e_[k] - d_[k], d_[k]);  // center cols @ y0
            const float rowC_n = fmaf(fx,  i_[k] - h_[k], h_[k]);  // center cols @ y0+1
            fC[k]  = fmaf(fy, rowC_n - rowC_c, rowC_c);

            const float rowL_c = fmaf(fxl, d_[k] - c_[k], c_[k]);
            const float rowL_n = fmaf(fxl, h_[k] - g_[k], g_[k]);
            fL[k]  = fmaf(fy, rowL_n - rowL_c, rowL_c);

            const float rowR_c = fmaf(fxr, f_[k] - e_[k], e_[k]);
            const float rowR_n = fmaf(fxr, j_[k] - i_[k], i_[k]);
            fR[k]  = fmaf(fy, rowR_n - rowR_c, rowR_c);

            const float rowT   = fmaf(fx,  b_[k] - a_[k], a_[k]);
            fT[k]  = fmaf(fyt, rowC_c - rowT, rowT);

            const float rowB   = fmaf(fx,  l_[k] - k_[k], k_[k]);
            fB4[k] = fmaf(fyb, rowB - rowC_n, rowC_n);
        }
    } else {
        // Fallback: 5 independent bilinear samples with bounds checks (exact).
        const float gxs[5] = {gx, gx - dx, gx + dx, gx,      gx     };
        const float gys[5] = {gy, gy,      gy,      gy - dy, gy + dy};
        float acc[5][4];
#pragma unroll
        for (int s = 0; s < 5; s++)
#pragma unroll
            for (int k = 0; k < 4; k++) acc[s][k] = 0.0f;

#pragma unroll
        for (int s = 0; s < 5; s++) {
            const float ixs = ((gxs[s] + 1.0f) * (float)WW - 1.0f) * 0.5f;
            const float iys = ((gys[s] + 1.0f) * (float)HH - 1.0f) * 0.5f;
            const float sx0f = floorf(ixs);
            const float sy0f = floorf(iys);
            const float wx1 = ixs - sx0f;
            const float wy1 = iys - sy0f;
            const float wx0 = 1.0f - wx1;
            const float wy0 = 1.0f - wy1;
            const int sx0 = (int)sx0f;
            const int sy0 = (int)sy0f;

            const int   xs[2]  = {sx0, sx0 + 1};
            const int   ys[2]  = {sy0, sy0 + 1};
            const float wxs[2] = {wx0, wx1};
            const float wys[2] = {wy0, wy1};

#pragma unroll
            for (int tyi = 0; tyi < 2; tyi++) {
#pragma unroll
                for (int txi = 0; txi < 2; txi++) {
                    const int xi = xs[txi];
                    const int yi = ys[tyi];
                    if (xi >= 0 && xi < WW && yi >= 0 && yi < HH) {
                        const float w = wxs[txi] * wys[tyi];
                        const float4 d =
                            __ldg((const float4*)(fb + ((size_t)yi * WW + xi) * CC));
                        acc[s][0] = fmaf(w, d.x, acc[s][0]);
                        acc[s][1] = fmaf(w, d.y, acc[s][1]);
                        acc[s][2] = fmaf(w, d.z, acc[s][2]);
                        acc[s][3] = fmaf(w, d.w, acc[s][3]);
                    }
                }
            }
        }
#pragma unroll
        for (int k = 0; k < 4; k++) {
            fC[k] = acc[0][k]; fL[k] = acc[1][k]; fR[k] = acc[2][k];
            fT[k] = acc[3][k]; fB4[k] = acc[4][k];
        }
    }

    // --- stage results in smem (conflict-free columns) ---
#pragma unroll
    for (int k = 0; k < 4; k++) {
        const int ch = cg * 4 + k;
        sF [ch][ptInBlk] = fC[k];
        sGx[ch][ptInBlk] = 0.5f * (fR[k] - fL[k]);
        sGy[ch][ptInBlk] = 0.5f * (fB4[k] - fT[k]);
    }

    __syncthreads();

    // --- coalesced store phase ---
    // thread -> (ch = tid>>4, grp = tid&15); handles 4 consecutive n.
    {
        const int ch  = tid >> 4;        // 0..15
        const int grp = tid & 15;        // 0..15
        const int n0  = blockIdx.x * 64 + grp * 4;
        if (n0 + 3 < Npts) {
            const int p0 = grp * 4;
            // f: (BV, C, N) — 16B-aligned v4 store, fully coalesced
            float4 vf = make_float4(sF[ch][p0], sF[ch][p0 + 1], sF[ch][p0 + 2], sF[ch][p0 + 3]);
            st_cs_v4((float4*)(out + ((size_t)bv * CC + ch) * Npts + n0), vf);

            // f_grad: (BV, C, N, 2) — two v4 stores = 4 (gx,gy) pairs
            float* gbase = out + (size_t)NBV * CC * Npts
                               + (((size_t)bv * CC + ch) * Npts + n0) * 2;
            float4 g01 = make_float4(sGx[ch][p0],     sGy[ch][p0],
                                     sGx[ch][p0 + 1], sGy[ch][p0 + 1]);
            float4 g23 = make_float4(sGx[ch][p0 + 2], sGy[ch][p0 + 2],
                                     sGx[ch][p0 + 3], sGy[ch][p0 + 3]);
            st_cs_v4((float4*)gbase,     g01);
            st_cs_v4((float4*)gbase + 1, g23);
        } else if (n0 < Npts) {
            // tail (not hit for N=131072, kept for safety)
            for (int j = 0; j < 4 && n0 + j < Npts; j++) {
                const int p = grp * 4 + j;
                out[((size_t)bv * CC + ch) * Npts + n0 + j] = sF[ch][p];
                float* gbase = out + (size_t)NBV * CC * Npts
                                   + (((size_t)bv * CC + ch) * Npts + n0 + j) * 2;
                gbase[0] = sGx[ch][p];
                gbase[1] = sGy[ch][p];
            }
        }
    }
}

// ---------------------------------------------------------------------------
// Launch. Inputs resolved by SIZE fingerprint:
//   fm = 52,428,800   pts = 786,432   K = 90   E = 120
// ---------------------------------------------------------------------------
extern "C" void kernel_launch(void* const* d_in, const int* in_sizes, int n_in,
                              void* d_out, int out_size) {
    const float* fm  = nullptr;
    const float* pts = nullptr;
    const float* K   = nullptr;
    const float* E   = nullptr;
    int pts_size = 0;

    for (int i = 0; i < n_in; i++) {
        const int s = in_sizes[i];
        if (s == NBV * 9) {
            K = (const float*)d_in[i];
        } else if (s == NBV * 12) {
            E = (const float*)d_in[i];
        } else if (s == (int)((size_t)NBV * CC * HW_)) {
            fm = (const float*)d_in[i];
        } else {
            pts = (const float*)d_in[i];
            pts_size = s;
        }
    }
    if (!fm || !pts || !K || !E) {
        fm  = (const float*)d_in[0];
        pts = (const float*)d_in[1];
        K   = (const float*)d_in[2];
        E   = (const float*)d_in[3];
        pts_size = in_sizes[1];
    }

    float* out = (float*)d_out;
    const int Npts = pts_size / (BB * 3);   // pts is (B, 3, N)

    dim3 tgrid(HW_ / 64, NBV);
    transpose_kernel<<<tgrid, 256>>>(fm);

    dim3 sgrid((Npts + 63) / 64, NBV);
    sample_kernel<<<sgrid, 256>>>(pts, K, E, out, Npts);
}